// round 7
// baseline (speedup 1.0000x reference)
#include <cuda_runtime.h>

#define S 32
#define NMAX 204800
#define MMAX 2048

#define GX 76
#define NC (GX * GX)
#define CELL 2.0f
#define ORG (-76.0f)
#define CBITS 13
#define CMASK ((1 << CBITS) - 1)
#define HITCAP 2048
#define TILE 2048
#define NTMAX 128

// ---------------- scratch (no allocations allowed) ----------------
__device__ float2 g_xy[NMAX];
__device__ int    g_flags[NMAX];
__device__ int    g_rankl[NMAX];
__device__ int    g_sidx[MMAX * S];
__device__ int    g_scount[MMAX];
__device__ int    g_cell[NMAX];      // packed: cell | (rank<<CBITS)
__device__ int    g_chist[NC];
__device__ int    g_cstart[NC + 2];
__device__ float2 g_cxy[NMAX];
__device__ int    g_cidx[NMAX];
__device__ unsigned long long g_tstate[NTMAX];  // lookback: (status<<32)|sum
__device__ int    g_total;
__device__ int    g_pdone;

__device__ __forceinline__ int cellc(float v) {
    int c = (int)floorf((v - ORG) * (1.0f / CELL));
    return min(max(c, 0), GX - 1);
}

// ---- warp-level sorted top-32 primitives (ascending) ----
__device__ __forceinline__ int warp_sort32(int v, int lane) {
    #pragma unroll
    for (int k = 2; k <= 32; k <<= 1) {
        #pragma unroll
        for (int j = k >> 1; j > 0; j >>= 1) {
            int o = __shfl_xor_sync(0xffffffffu, v, j);
            bool keepMin = (((lane & j) == 0) == ((lane & k) == 0));
            v = keepMin ? min(v, o) : max(v, o);
        }
    }
    return v;
}
__device__ __forceinline__ int warp_bmerge32(int v, int lane) {
    #pragma unroll
    for (int j = 16; j > 0; j >>= 1) {
        int o = __shfl_xor_sync(0xffffffffu, v, j);
        v = ((lane & j) == 0) ? min(v, o) : max(v, o);
    }
    return v;
}
__device__ __forceinline__ int warp_topk_merge(int a, int b, int lane) {
    int br = __shfl_sync(0xffffffffu, b, 31 - lane);
    return warp_bmerge32(min(a, br), lane);
}

// ---------------- K1: pack + hist + (last block) cell prefix ----------------
__global__ void __launch_bounds__(256) k_pack(const float* __restrict__ pts, int N) {
    __shared__ int sh_cnt[NC];            // counts, then overwritten with block bases
    __shared__ int s_last;
    int t = threadIdx.x;
    for (int c = t; c < NC; c += 256) sh_cnt[c] = 0;
    __syncthreads();

    int i0 = (blockIdx.x * 256 + t) * 4;
    float2 P[4];
    int cell[4], lr[4];
    bool val[4];
    if (i0 + 4 <= N) {
        const float4* p4 = (const float4*)(pts + (size_t)i0 * 5);
        float4 v[5];
        #pragma unroll
        for (int k = 0; k < 5; k++) v[k] = p4[k];
        const float* f = (const float*)v;
        #pragma unroll
        for (int k = 0; k < 4; k++) { P[k] = make_float2(f[5 * k], f[5 * k + 1]); val[k] = true; }
    } else {
        #pragma unroll
        for (int k = 0; k < 4; k++) {
            int i = i0 + k;
            val[k] = (i < N);
            P[k] = val[k] ? make_float2(pts[i * 5], pts[i * 5 + 1]) : make_float2(0.f, 0.f);
        }
    }
    #pragma unroll
    for (int k = 0; k < 4; k++) {
        if (val[k]) {
            int i = i0 + k;
            g_xy[i] = P[k];
            g_flags[i] = 0;
            cell[k] = cellc(P[k].y) * GX + cellc(P[k].x);
            lr[k] = atomicAdd(&sh_cnt[cell[k]], 1);
        }
    }
    __syncthreads();
    for (int c = t; c < NC; c += 256) {
        int n = sh_cnt[c];
        int base = n ? atomicAdd(&g_chist[c], n) : 0;
        sh_cnt[c] = base;    // overwrite count with this block's base
    }
    __syncthreads();
    #pragma unroll
    for (int k = 0; k < 4; k++)
        if (val[k]) g_cell[i0 + k] = cell[k] | ((sh_cnt[cell[k]] + lr[k]) << CBITS);

    // ---- last-done block computes the cell prefix ----
    __threadfence();
    if (t == 0) s_last = (atomicAdd(&g_pdone, 1) == (int)gridDim.x - 1);
    __syncthreads();
    if (!s_last) return;

    const int PER = (NC + 255) / 256;     // 23
    __shared__ int wofs2[8];
    int lane = t & 31, wid = t >> 5;
    int v[PER];
    int sum = 0;
    #pragma unroll
    for (int k = 0; k < PER; k++) {
        int idx = t * PER + k;
        int x = (idx < NC) ? g_chist[idx] : 0;
        v[k] = sum;                        // thread-local exclusive
        sum += x;
    }
    int inc = sum;
    #pragma unroll
    for (int off = 1; off < 32; off <<= 1) {
        int x = __shfl_up_sync(0xffffffffu, inc, off);
        if (lane >= off) inc += x;
    }
    int exc = inc - sum;
    if (lane == 31) wofs2[wid] = inc;
    __syncthreads();
    if (wid == 0) {
        int w = (lane < 8) ? wofs2[lane] : 0;
        int iw = w;
        #pragma unroll
        for (int off = 1; off < 8; off <<= 1) {
            int x = __shfl_up_sync(0xffffffffu, iw, off);
            if (lane >= off) iw += x;
        }
        if (lane < 8) wofs2[lane] = iw - w;
    }
    __syncthreads();
    int toff = exc + wofs2[wid];
    #pragma unroll
    for (int k = 0; k < PER; k++) {
        int idx = t * PER + k;
        if (idx < NC) { g_cstart[idx] = toff + v[k]; g_chist[idx] = 0; }
    }
    if (t == 255) g_cstart[NC] = toff + sum;   // grand total (for cell NC-1's end)
    if (t == 0) g_pdone = 0;                   // reset for next replay
}

// ---------------- K3: atomic-free scatter into cell lists ----------------
__global__ void __launch_bounds__(256) k_fill(int N) {
    int i = blockIdx.x * 256 + threadIdx.x;
    if (i < N) {
        int pc = g_cell[i];
        int pos = g_cstart[pc & CMASK] + (pc >> CBITS);
        g_cxy[pos] = g_xy[i];
        g_cidx[pos] = i;
    }
}

// ---------------- K4: per-box selection via grid + warp top-32 ----------------
__global__ void __launch_bounds__(256) k_boxes(const float* __restrict__ boxes, int N) {
    int m = blockIdx.x;
    int tid = threadIdx.x;
    int lane = tid & 31, wid = tid >> 5;
    float bx = boxes[m * 7 + 0];
    float by = boxes[m * 7 + 1];
    float hx = __fmul_rn(boxes[m * 7 + 3], 0.5f);
    float hy = __fmul_rn(boxes[m * 7 + 4], 0.5f);
    float r  = __fmul_rn(sqrtf(__fadd_rn(__fmul_rn(hx, hx), __fmul_rn(hy, hy))), 1.1f);

    __shared__ int s_hit[HITCAP];
    __shared__ int s_ws[8][S];
    __shared__ int s_cnt, s_c;
    __shared__ int s_m[S], s_u[S];
    if (tid == 0) s_cnt = 0;
    __syncthreads();

    int cx0 = cellc(bx - r - 0.5f), cx1 = cellc(bx + r + 0.5f);
    int cy0 = cellc(by - r - 0.5f), cy1 = cellc(by + r + 0.5f);

    for (int cy = cy0; cy <= cy1; cy++) {
        int s0 = g_cstart[cy * GX + cx0];
        int s1 = g_cstart[cy * GX + cx1 + 1];
        for (int i = s0 + tid; i < s1; i += 256) {
            float2 p = g_cxy[i];
            float dx = __fadd_rn(bx, -p.x);
            float dy = __fadd_rn(by, -p.y);
            float d2 = __fadd_rn(__fmul_rn(dx, dx), __fmul_rn(dy, dy));
            if (sqrtf(d2) <= r) {
                int pos = atomicAdd(&s_cnt, 1);
                if (pos < HITCAP) s_hit[pos] = g_cidx[i];
            }
        }
    }
    __syncthreads();
    int cnt = s_cnt;

    if (cnt <= HITCAP) {
        int best = 0x7fffffff;
        bool first = true;
        for (int b = wid * 32; b < cnt; b += 256) {
            int idx = b + lane;
            int v = (idx < cnt) ? s_hit[idx] : 0x7fffffff;
            v = warp_sort32(v, lane);
            best = first ? v : warp_topk_merge(best, v, lane);
            first = false;
        }
        s_ws[wid][lane] = best;
        __syncthreads();
        if (wid == 0) {
            int acc = s_ws[0][lane];
            #pragma unroll
            for (int w = 1; w < 8; w++)
                acc = warp_topk_merge(acc, s_ws[w][lane], lane);
            int c = min(cnt, S);
            if (lane < c) s_m[lane] = acc;
            if (lane == 0) s_c = c;
        }
    } else {
        if (tid < 32) {
            int got = 0;
            for (int base = 0; got < S && base < N; base += 32) {
                int i = base + lane;
                bool mem = false;
                if (i < N) {
                    float2 p = g_xy[i];
                    float dx = __fadd_rn(bx, -p.x);
                    float dy = __fadd_rn(by, -p.y);
                    float d2 = __fadd_rn(__fmul_rn(dx, dx), __fmul_rn(dy, dy));
                    mem = (sqrtf(d2) <= r);
                }
                unsigned bmask = __ballot_sync(0xffffffffu, mem);
                int before = __popc(bmask & ((1u << lane) - 1));
                if (mem && got + before < S) s_m[got + before] = i;
                got += __popc(bmask);
            }
            if (lane == 0) s_c = S;
        }
    }
    __syncthreads();
    int c = s_c;

    if (c < S) {
        if (tid < 32) {
            int need = S - c;
            int got = 0;
            for (int base = 0; got < need && base < N; base += 32) {
                int i = base + lane;
                bool nm = false;
                if (i < N) {
                    float2 p = g_xy[i];
                    float dx = __fadd_rn(bx, -p.x);
                    float dy = __fadd_rn(by, -p.y);
                    float d2 = __fadd_rn(__fmul_rn(dx, dx), __fmul_rn(dy, dy));
                    nm = !(sqrtf(d2) <= r);
                }
                unsigned bmask = __ballot_sync(0xffffffffu, nm);
                int before = __popc(bmask & ((1u << lane) - 1));
                if (nm && got + before < need) s_u[got + before] = i;
                got += __popc(bmask);
            }
        }
        __syncthreads();
    }

    if (tid < S) {
        int v = (tid < c) ? s_m[tid] : s_u[tid - c];
        g_sidx[m * S + tid] = v;
        g_flags[v] = 1;   // benign race: all writers store 1
    }
    if (tid == 0) g_scount[m] = c;
}

// ---------------- K5: single-pass rank scan (warp-parallel lookback) + qp scatter ----------------
__global__ void __launch_bounds__(256) k_scan(const float* __restrict__ pts,
                                              float* __restrict__ qp, int N) {
    __shared__ int wsums[8];
    __shared__ int s_total;
    __shared__ int s_off;
    int bid = blockIdx.x, t = threadIdx.x, lane = t & 31, wid = t >> 5;
    int i0 = bid * TILE + t * 8;

    int fl[8];
    {
        const int4* fp = (const int4*)&g_flags[i0];
        int4 a = fp[0], b = fp[1];
        fl[0] = a.x; fl[1] = a.y; fl[2] = a.z; fl[3] = a.w;
        fl[4] = b.x; fl[5] = b.y; fl[6] = b.z; fl[7] = b.w;
    }
    int tsum = 0;
    #pragma unroll
    for (int k = 0; k < 8; k++) { if (i0 + k >= N) fl[k] = 0; tsum += fl[k]; }

    int inc = tsum;
    #pragma unroll
    for (int off = 1; off < 32; off <<= 1) {
        int v = __shfl_up_sync(0xffffffffu, inc, off);
        if (lane >= off) inc += v;
    }
    int exc = inc - tsum;
    if (lane == 31) wsums[wid] = inc;
    __syncthreads();
    if (wid == 0) {
        int v = (lane < 8) ? wsums[lane] : 0;
        int iv = v;
        #pragma unroll
        for (int off = 1; off < 8; off <<= 1) {
            int x = __shfl_up_sync(0xffffffffu, iv, off);
            if (lane >= off) iv += x;
        }
        if (lane == 7) s_total = iv;
        if (lane < 8) wsums[lane] = iv - v;
    }
    __syncthreads();
    int texc = exc + wsums[wid];

    if (wid == 0) {
        int total = s_total;
        if (bid == 0) {
            if (lane == 0) {
                atomicExch(&g_tstate[0], (2ULL << 32) | (unsigned)total);
                s_off = 0;
                if ((int)gridDim.x == 1) g_total = total;
            }
        } else {
            if (lane == 0) atomicExch(&g_tstate[bid], (1ULL << 32) | (unsigned)total);
            __syncwarp();
            long long off = 0;
            int j = bid - 1;
            while (1) {
                int idx = j - lane;
                unsigned long long st = 0;
                if (idx >= 0) {
                    do { st = atomicAdd(&g_tstate[idx], 0ULL); } while ((st >> 32) == 0ULL);
                }
                unsigned pmask = __ballot_sync(0xffffffffu, idx >= 0 && (st >> 32) == 2ULL);
                unsigned v;
                if (pmask) {
                    int l2 = __ffs(pmask) - 1;
                    v = (lane <= l2) ? (unsigned)st : 0u;
                } else {
                    v = (idx >= 0) ? (unsigned)st : 0u;
                }
                #pragma unroll
                for (int o = 16; o; o >>= 1) v += __shfl_down_sync(0xffffffffu, v, o);
                v = __shfl_sync(0xffffffffu, v, 0);
                off += v;
                if (pmask || (j -= 32) < 0) break;
            }
            if (lane == 0) {
                atomicExch(&g_tstate[bid], (2ULL << 32) | (unsigned)(off + total));
                s_off = (int)off;
                if (bid == (int)gridDim.x - 1) g_total = (int)off + total;
            }
        }
    }
    __syncthreads();

    int run = s_off + texc;
    #pragma unroll
    for (int k = 0; k < 8; k++) {
        int i = i0 + k;
        if (i < N) {
            g_rankl[i] = run;
            if (fl[k]) {
                const float* src = pts + (size_t)i * 5;
                float* dst = qp + (size_t)run * 5;
                dst[0] = src[0]; dst[1] = src[1]; dst[2] = src[2];
                dst[3] = src[3]; dst[4] = src[4];
                run++;
            }
        }
    }
}

// ---------------- K6: sampled_points + idx + qp padding + state reset ----------------
__global__ void k_out(const float* __restrict__ pts, float* __restrict__ outp,
                      float* __restrict__ outi, float* __restrict__ qp, int M) {
    int t = blockIdx.x * blockDim.x + threadIdx.x;
    if (t < NTMAX) g_tstate[t] = 0ULL;   // reset for next replay
    if (t < M * S) {
        int m = t >> 5, j = t & 31;
        int c = g_scount[m];
        int p = g_sidx[t];
        bool msk = (j < c);
        outi[t] = msk ? (float)g_rankl[p] : 0.0f;
        #pragma unroll
        for (int cc = 0; cc < 5; cc++)
            outp[t * 5 + cc] = msk ? pts[p * 5 + cc] : 0.0f;
        if (t >= g_total) {
            #pragma unroll
            for (int cc = 0; cc < 5; cc++) qp[t * 5 + cc] = pts[cc];
        }
    }
}

// ---------------- launch ----------------
extern "C" void kernel_launch(void* const* d_in, const int* in_sizes, int n_in,
                              void* d_out, int out_size) {
    const float* pts   = (const float*)d_in[0];
    const float* boxes = (const float*)d_in[1];
    int N = in_sizes[0] / 5;
    int M = in_sizes[1] / 7;
    if (N > NMAX) N = NMAX;
    if (M > MMAX) M = MMAX;

    float* out  = (float*)d_out;
    float* outp = out;                            // sampled_points [M*S*5]
    float* outi = out + (size_t)M * S * 5;        // idx            [M*S]
    float* qp   = outi + (size_t)M * S;           // query_points   [M*S*5]

    int NT = (N + TILE - 1) / TILE;

    k_pack<<<(N + 1023) / 1024, 256>>>(pts, N);
    k_fill<<<(N + 255) / 256, 256>>>(N);
    k_boxes<<<M, 256>>>(boxes, N);
    k_scan<<<NT, 256>>>(pts, qp, N);
    k_out<<<(M * S + 255) / 256, 256>>>(pts, outp, outi, qp, M);
}

// round 8
// speedup vs baseline: 1.3024x; 1.3024x over previous
#include <cuda_runtime.h>

#define S 32
#define NMAX 204800
#define MMAX 2048

#define GX 38
#define NC (GX * GX)
#define CELL 4.0f
#define ORG (-76.0f)
#define CBITS 11
#define CMASK ((1 << CBITS) - 1)
#define HITCAP 2048
#define NWORDS ((NMAX + 31) / 32)

// ---------------- scratch (no allocations allowed) ----------------
__device__ float2 g_xy[NMAX];
__device__ unsigned g_bits[NWORDS];   // flag bitmask (zero-init; k_out re-clears)
__device__ int    g_wrank[NWORDS];    // exclusive popc prefix per word
__device__ int    g_rankl[NMAX];      // rank, valid at flagged positions only
__device__ int    g_sidx[MMAX * S];
__device__ int    g_scount[MMAX];
__device__ int    g_cell[NMAX];       // packed: cell | (rank<<CBITS)
__device__ int    g_chist[NC];
__device__ int    g_cstart[NC + 2];
__device__ float2 g_cxy[NMAX];
__device__ int    g_cidx[NMAX];
__device__ int    g_total;

__device__ __forceinline__ int cellc(float v) {
    int c = (int)floorf((v - ORG) * (1.0f / CELL));
    return min(max(c, 0), GX - 1);
}

// ---- warp-level sorted top-32 primitives (ascending) ----
__device__ __forceinline__ int warp_sort32(int v, int lane) {
    #pragma unroll
    for (int k = 2; k <= 32; k <<= 1) {
        #pragma unroll
        for (int j = k >> 1; j > 0; j >>= 1) {
            int o = __shfl_xor_sync(0xffffffffu, v, j);
            bool keepMin = (((lane & j) == 0) == ((lane & k) == 0));
            v = keepMin ? min(v, o) : max(v, o);
        }
    }
    return v;
}
__device__ __forceinline__ int warp_bmerge32(int v, int lane) {
    #pragma unroll
    for (int j = 16; j > 0; j >>= 1) {
        int o = __shfl_xor_sync(0xffffffffu, v, j);
        v = ((lane & j) == 0) ? min(v, o) : max(v, o);
    }
    return v;
}
__device__ __forceinline__ int warp_topk_merge(int a, int b, int lane) {
    int br = __shfl_sync(0xffffffffu, b, 31 - lane);
    return warp_bmerge32(min(a, br), lane);
}

// ---------------- K1: pack xy + hierarchical histogram ----------------
__global__ void __launch_bounds__(256) k_pack(const float* __restrict__ pts, int N) {
    __shared__ int sh_cnt[NC];
    __shared__ int sh_base[NC];
    int t = threadIdx.x;
    for (int c = t; c < NC; c += 256) sh_cnt[c] = 0;
    __syncthreads();

    int i0 = (blockIdx.x * 256 + t) * 4;
    float2 P[4];
    int cell[4], lr[4];
    bool val[4];
    if (i0 + 4 <= N) {
        const float4* p4 = (const float4*)(pts + (size_t)i0 * 5);
        float4 v[5];
        #pragma unroll
        for (int k = 0; k < 5; k++) v[k] = p4[k];
        const float* f = (const float*)v;
        #pragma unroll
        for (int k = 0; k < 4; k++) { P[k] = make_float2(f[5 * k], f[5 * k + 1]); val[k] = true; }
    } else {
        #pragma unroll
        for (int k = 0; k < 4; k++) {
            int i = i0 + k;
            val[k] = (i < N);
            P[k] = val[k] ? make_float2(pts[i * 5], pts[i * 5 + 1]) : make_float2(0.f, 0.f);
        }
    }
    #pragma unroll
    for (int k = 0; k < 4; k++) {
        if (val[k]) {
            int i = i0 + k;
            g_xy[i] = P[k];
            cell[k] = cellc(P[k].y) * GX + cellc(P[k].x);
            lr[k] = atomicAdd(&sh_cnt[cell[k]], 1);
        }
    }
    __syncthreads();
    for (int c = t; c < NC; c += 256) {
        int n = sh_cnt[c];
        sh_base[c] = n ? atomicAdd(&g_chist[c], n) : 0;
    }
    __syncthreads();
    #pragma unroll
    for (int k = 0; k < 4; k++)
        if (val[k]) g_cell[i0 + k] = cell[k] | ((sh_base[cell[k]] + lr[k]) << CBITS);
}

// ---------------- K2: exclusive prefix over cell histogram + reset hist ----------------
__global__ void __launch_bounds__(1024) k_prefix() {
    __shared__ int wofs[32];
    int tid = threadIdx.x, lane = tid & 31, wid = tid >> 5;
    int a = 0, b = 0;
    if (2 * tid < NC)     { a = g_chist[2 * tid];     g_chist[2 * tid] = 0; }
    if (2 * tid + 1 < NC) { b = g_chist[2 * tid + 1]; g_chist[2 * tid + 1] = 0; }
    int s = a + b;
    int inc = s;
    #pragma unroll
    for (int off = 1; off < 32; off <<= 1) {
        int v = __shfl_up_sync(0xffffffffu, inc, off);
        if (lane >= off) inc += v;
    }
    if (lane == 31) wofs[wid] = inc;
    __syncthreads();
    if (wid == 0) {
        int v = wofs[lane];
        int iv = v;
        #pragma unroll
        for (int off = 1; off < 32; off <<= 1) {
            int t2 = __shfl_up_sync(0xffffffffu, iv, off);
            if (lane >= off) iv += t2;
        }
        wofs[lane] = iv - v;
    }
    __syncthreads();
    int exc = inc - s + wofs[wid];
    if (2 * tid     <= NC + 1) g_cstart[2 * tid]     = exc;
    if (2 * tid + 1 <= NC + 1) g_cstart[2 * tid + 1] = exc + a;
}

// ---------------- K3: atomic-free scatter into cell lists ----------------
__global__ void __launch_bounds__(256) k_fill(int N) {
    int i = blockIdx.x * 256 + threadIdx.x;
    if (i < N) {
        int pc = g_cell[i];
        int pos = g_cstart[pc & CMASK] + (pc >> CBITS);
        g_cxy[pos] = g_xy[i];
        g_cidx[pos] = i;
    }
}

// ---------------- K4: per-box selection via grid + warp top-32 ----------------
__global__ void __launch_bounds__(256) k_boxes(const float* __restrict__ boxes, int N) {
    int m = blockIdx.x;
    int tid = threadIdx.x;
    int lane = tid & 31, wid = tid >> 5;
    float bx = boxes[m * 7 + 0];
    float by = boxes[m * 7 + 1];
    float hx = __fmul_rn(boxes[m * 7 + 3], 0.5f);
    float hy = __fmul_rn(boxes[m * 7 + 4], 0.5f);
    float r  = __fmul_rn(sqrtf(__fadd_rn(__fmul_rn(hx, hx), __fmul_rn(hy, hy))), 1.1f);

    __shared__ int s_hit[HITCAP];
    __shared__ int s_ws[8][S];
    __shared__ int s_cnt, s_c;
    __shared__ int s_m[S], s_u[S];
    if (tid == 0) s_cnt = 0;
    __syncthreads();

    int cx0 = cellc(bx - r - 0.5f), cx1 = cellc(bx + r + 0.5f);
    int cy0 = cellc(by - r - 0.5f), cy1 = cellc(by + r + 0.5f);

    for (int cy = cy0; cy <= cy1; cy++) {
        int s0 = g_cstart[cy * GX + cx0];
        int s1 = g_cstart[cy * GX + cx1 + 1];
        for (int i = s0 + tid; i < s1; i += 256) {
            float2 p = g_cxy[i];
            float dx = __fadd_rn(bx, -p.x);
            float dy = __fadd_rn(by, -p.y);
            float d2 = __fadd_rn(__fmul_rn(dx, dx), __fmul_rn(dy, dy));
            if (sqrtf(d2) <= r) {
                int pos = atomicAdd(&s_cnt, 1);
                if (pos < HITCAP) s_hit[pos] = g_cidx[i];
            }
        }
    }
    __syncthreads();
    int cnt = s_cnt;

    if (cnt <= HITCAP) {
        int best = 0x7fffffff;
        bool first = true;
        for (int b = wid * 32; b < cnt; b += 256) {
            int idx = b + lane;
            int v = (idx < cnt) ? s_hit[idx] : 0x7fffffff;
            v = warp_sort32(v, lane);
            best = first ? v : warp_topk_merge(best, v, lane);
            first = false;
        }
        s_ws[wid][lane] = best;
        __syncthreads();
        if (wid == 0) {
            int acc = s_ws[0][lane];
            #pragma unroll
            for (int w = 1; w < 8; w++)
                acc = warp_topk_merge(acc, s_ws[w][lane], lane);
            int c = min(cnt, S);
            if (lane < c) s_m[lane] = acc;
            if (lane == 0) s_c = c;
        }
    } else {
        if (tid < 32) {
            int got = 0;
            for (int base = 0; got < S && base < N; base += 32) {
                int i = base + lane;
                bool mem = false;
                if (i < N) {
                    float2 p = g_xy[i];
                    float dx = __fadd_rn(bx, -p.x);
                    float dy = __fadd_rn(by, -p.y);
                    float d2 = __fadd_rn(__fmul_rn(dx, dx), __fmul_rn(dy, dy));
                    mem = (sqrtf(d2) <= r);
                }
                unsigned bmask = __ballot_sync(0xffffffffu, mem);
                int before = __popc(bmask & ((1u << lane) - 1));
                if (mem && got + before < S) s_m[got + before] = i;
                got += __popc(bmask);
            }
            if (lane == 0) s_c = S;
        }
    }
    __syncthreads();
    int c = s_c;

    if (c < S) {
        if (tid < 32) {
            int need = S - c;
            int got = 0;
            for (int base = 0; got < need && base < N; base += 32) {
                int i = base + lane;
                bool nm = false;
                if (i < N) {
                    float2 p = g_xy[i];
                    float dx = __fadd_rn(bx, -p.x);
                    float dy = __fadd_rn(by, -p.y);
                    float d2 = __fadd_rn(__fmul_rn(dx, dx), __fmul_rn(dy, dy));
                    nm = !(sqrtf(d2) <= r);
                }
                unsigned bmask = __ballot_sync(0xffffffffu, nm);
                int before = __popc(bmask & ((1u << lane) - 1));
                if (nm && got + before < need) s_u[got + before] = i;
                got += __popc(bmask);
            }
        }
        __syncthreads();
    }

    if (tid < S) {
        int v = (tid < c) ? s_m[tid] : s_u[tid - c];
        g_sidx[m * S + tid] = v;
        atomicOr(&g_bits[v >> 5], 1u << (v & 31));
    }
    if (tid == 0) g_scount[m] = c;
}

// ---------------- K5: single-block popc prefix over flag words ----------------
__global__ void __launch_bounds__(1024) k_wprefix() {
    const int PER = (NWORDS + 1023) / 1024;   // 7
    __shared__ int wofs[32];
    int t = threadIdx.x, lane = t & 31, wid = t >> 5;
    int loc[PER];
    int sum = 0;
    #pragma unroll
    for (int k = 0; k < PER; k++) {
        int idx = t * PER + k;
        int p = (idx < NWORDS) ? __popc(g_bits[idx]) : 0;
        loc[k] = sum;
        sum += p;
    }
    int inc = sum;
    #pragma unroll
    for (int off = 1; off < 32; off <<= 1) {
        int v = __shfl_up_sync(0xffffffffu, inc, off);
        if (lane >= off) inc += v;
    }
    int exc = inc - sum;
    if (lane == 31) wofs[wid] = inc;
    __syncthreads();
    if (wid == 0) {
        int v = wofs[lane];
        int iv = v;
        #pragma unroll
        for (int off = 1; off < 32; off <<= 1) {
            int x = __shfl_up_sync(0xffffffffu, iv, off);
            if (lane >= off) iv += x;
        }
        wofs[lane] = iv - v;
        if (lane == 31) g_total = iv;
    }
    __syncthreads();
    int base = exc + wofs[wid];
    #pragma unroll
    for (int k = 0; k < PER; k++) {
        int idx = t * PER + k;
        if (idx < NWORDS) g_wrank[idx] = base + loc[k];
    }
}

// ---------------- K6: per-point rank + qp scatter (bitmask-driven) ----------------
__global__ void __launch_bounds__(256) k_rank(const float* __restrict__ pts,
                                              float* __restrict__ qp, int N) {
    int i = blockIdx.x * 256 + threadIdx.x;
    if (i >= N) return;
    int w = i >> 5, bit = i & 31;
    unsigned word = g_bits[w];            // one load per warp (broadcast)
    if ((word >> bit) & 1u) {
        int rank = g_wrank[w] + __popc(word & ((1u << bit) - 1u));
        g_rankl[i] = rank;
        const float* src = pts + (size_t)i * 5;
        float* dst = qp + (size_t)rank * 5;
        dst[0] = src[0]; dst[1] = src[1]; dst[2] = src[2];
        dst[3] = src[3]; dst[4] = src[4];
    }
}

// ---------------- K7: sampled_points + idx + qp padding + bitmask reset ----------------
__global__ void k_out(const float* __restrict__ pts, float* __restrict__ outp,
                      float* __restrict__ outi, float* __restrict__ qp, int M) {
    int t = blockIdx.x * blockDim.x + threadIdx.x;
    if (t < NWORDS) g_bits[t] = 0u;   // reset for next replay
    if (t < M * S) {
        int m = t >> 5, j = t & 31;
        int c = g_scount[m];
        int p = g_sidx[t];
        bool msk = (j < c);
        outi[t] = msk ? (float)g_rankl[p] : 0.0f;
        #pragma unroll
        for (int cc = 0; cc < 5; cc++)
            outp[t * 5 + cc] = msk ? pts[p * 5 + cc] : 0.0f;
        if (t >= g_total) {
            #pragma unroll
            for (int cc = 0; cc < 5; cc++) qp[t * 5 + cc] = pts[cc];
        }
    }
}

// ---------------- launch ----------------
extern "C" void kernel_launch(void* const* d_in, const int* in_sizes, int n_in,
                              void* d_out, int out_size) {
    const float* pts   = (const float*)d_in[0];
    const float* boxes = (const float*)d_in[1];
    int N = in_sizes[0] / 5;
    int M = in_sizes[1] / 7;
    if (N > NMAX) N = NMAX;
    if (M > MMAX) M = MMAX;

    float* out  = (float*)d_out;
    float* outp = out;                            // sampled_points [M*S*5]
    float* outi = out + (size_t)M * S * 5;        // idx            [M*S]
    float* qp   = outi + (size_t)M * S;           // query_points   [M*S*5]

    k_pack<<<(N + 1023) / 1024, 256>>>(pts, N);
    k_prefix<<<1, 1024>>>();
    k_fill<<<(N + 255) / 256, 256>>>(N);
    k_boxes<<<M, 256>>>(boxes, N);
    k_wprefix<<<1, 1024>>>();
    k_rank<<<(N + 255) / 256, 256>>>(pts, qp, N);
    k_out<<<(M * S + 255) / 256, 256>>>(pts, outp, outi, qp, M);
}